// round 10
// baseline (speedup 1.0000x reference)
#include <cuda_runtime.h>
#include <cstddef>

// ---------------------------------------------------------------------------
// Compile-time Gaussian weights (passed BY VALUE so they fold to FFMA-imm)
// ---------------------------------------------------------------------------
constexpr double cexp_pos(double x) {
    double term = 1.0, sum = 1.0;
    for (int i = 1; i < 200; ++i) {
        term *= x / (double)i;
        if (term < 1e-250) break;
        sum += term;
    }
    return sum;
}

template <int KS>
struct Wt { float w[KS]; };

template <int KS>
constexpr Wt<KS> make_w(double sigma) {
    Wt<KS> W{};
    double wd[KS]{};
    double s = 0.0;
    for (int i = 0; i < KS; ++i) {
        double d = (double)(i - KS / 2);
        double e = 1.0 / cexp_pos(d * d / (2.0 * sigma * sigma));
        wd[i] = e;
        s += e;
    }
    for (int i = 0; i < KS; ++i) W.w[i] = (float)(wd[i] / s);
    return W;
}

constexpr Wt<7>   CW0 = make_w<7>(0.6);
constexpr Wt<9>   CW1 = make_w<9>(1.2);
constexpr Wt<17>  CW2 = make_w<17>(2.4);
constexpr Wt<31>  CW3 = make_w<31>(4.8);
constexpr Wt<59>  CW4 = make_w<59>(9.6);
constexpr Wt<117> CW5 = make_w<117>(19.2);

constexpr int H = 512, W = 512;
constexpr int HW = H * W;
constexpr int NROWS = 8 * 3 * H;        // 12288
constexpr int NPIX = NROWS * W;         // 6291456
constexpr int PMAX = 58;

__device__ float g_scratch[6 * (size_t)NPIX];

// ---------------------------------------------------------------------------
// cp.async helpers
// ---------------------------------------------------------------------------
__device__ __forceinline__ void cp_async16(unsigned daddr, const void* gsrc) {
    asm volatile("cp.async.cg.shared.global [%0], [%1], 16;\n"
                 :: "r"(daddr), "l"(gsrc) : "memory");
}
__device__ __forceinline__ void cp_async4(unsigned daddr, const void* gsrc) {
    asm volatile("cp.async.ca.shared.global [%0], [%1], 4;\n"
                 :: "r"(daddr), "l"(gsrc) : "memory");
}
__device__ __forceinline__ void cp_commit() {
    asm volatile("cp.async.commit_group;\n" ::: "memory");
}
template <int N>
__device__ __forceinline__ void cp_wait() {
    asm volatile("cp.async.wait_group %0;\n" :: "n"(N) : "memory");
}

// ---------------------------------------------------------------------------
// Kernel A: horizontal pass — persistent, cp.async double-buffered.
// CTA = 256 thr = 4 rows x 64 lanes; 8 px/lane; each CTA does NITER=4
// row-groups. While computing group i, group i+1 streams into the other
// smem buffer. Padded smem row (idx -> idx + idx/8): conflict-free.
// ---------------------------------------------------------------------------
constexpr int HNITER = 4;
constexpr int HGRID  = NROWS / (4 * HNITER);   // 768

template <int KS>
__device__ __forceinline__ void hconv(const Wt<KS> Wc,
                                      const float* __restrict__ sr,
                                      int lane, float* __restrict__ dst) {
    constexpr int P  = KS / 2;
    constexpr int S0 = PMAX - P;
    constexpr int Q  = S0 >> 3;
    constexpr int R  = S0 & 7;
    const int base = 9 * (lane + Q);

    float win[8], acc[8];
#pragma unroll
    for (int i = 0; i < 7; ++i)
        win[i] = sr[base + (R + i) + ((R + i) >> 3)];
#pragma unroll
    for (int t = 0; t < 8; ++t) acc[t] = 0.f;
#pragma unroll
    for (int k = 0; k < KS; ++k) {
        const int j = k + 7;
        win[j & 7] = sr[base + (R + j) + ((R + j) >> 3)];
#pragma unroll
        for (int t = 0; t < 8; ++t)
            acc[t] += Wc.w[k] * win[(k + t) & 7];
    }
    float4* d4 = reinterpret_cast<float4*>(dst + lane * 8);
    d4[0] = make_float4(acc[0], acc[1], acc[2], acc[3]);
    d4[1] = make_float4(acc[4], acc[5], acc[6], acc[7]);
}

__global__ __launch_bounds__(256) void hpass_kernel(const float* __restrict__ img) {
    __shared__ float sr[2][4][712];
    const int grp = threadIdx.x >> 6;      // row within group (0..3)
    const int lt  = threadIdx.x & 63;
    const int row0 = blockIdx.x * (4 * HNITER) + grp;

    const unsigned smb = (unsigned)__cvta_generic_to_shared(&sr[0][0][0]);

    // async halo load of row-group `it` into buffer `buf`
    auto issue = [&](int it, int buf) {
        const float* rp = img + (size_t)(row0 + it * 4) * W;
        const unsigned dbase = smb + (unsigned)(buf * 4 + grp) * (712u * 4u);
        for (int x = lt; x < W + 2 * PMAX; x += 64) {
            int gx = x - PMAX;
            gx = gx < 0 ? -gx : (gx > W - 1 ? 2 * W - 2 - gx : gx);
            cp_async4(dbase + (unsigned)(x + (x >> 3)) * 4u, rp + gx);
        }
    };

    issue(0, 0);
    cp_commit();

    for (int i = 0; i < HNITER; ++i) {
        if (i + 1 < HNITER) issue(i + 1, (i + 1) & 1);
        cp_commit();                       // empty group on last iter keeps
        cp_wait<1>();                      // wait count compile-time constant
        __syncthreads();

        const float* s = sr[i & 1][grp];
        float* base = g_scratch + (size_t)(row0 + i * 4) * W;
        hconv<7>(CW0, s, lt, base + 0 * (size_t)NPIX);
        hconv<9>(CW1, s, lt, base + 1 * (size_t)NPIX);
        hconv<17>(CW2, s, lt, base + 2 * (size_t)NPIX);
        hconv<31>(CW3, s, lt, base + 3 * (size_t)NPIX);
        hconv<59>(CW4, s, lt, base + 4 * (size_t)NPIX);
        hconv<117>(CW5, s, lt, base + 5 * (size_t)NPIX);
        __syncthreads();                   // all reads done before next overwrite
    }
}

// ---------------------------------------------------------------------------
// Kernel B: vertical pass + DoG, double-buffered, DESCENDING sigma order
// (exact round-8 proven version: 71.4 us).
// Slot A (180 rows) holds sigma 5,3,1 tiles; slot B (122 rows) holds 4,2,0.
// smem = 302 rows * 128 B = 38656 B -> 5 CTAs/SM.
// ---------------------------------------------------------------------------
constexpr int VSMEM_BYTES = 302 * 32 * 4;    // 38656
constexpr int BUFA = 0;                       // 180 rows
constexpr int BUFB = 180 * 32;                // 122 rows

template <int KS, int OFF>
__device__ __forceinline__ void load_tile_async(unsigned smb,
                                                const float* __restrict__ src,
                                                int R0, int tid) {
    constexpr int P  = KS / 2;
    constexpr int NR = 64 + KS - 1;
    const unsigned base = smb + (unsigned)OFF * 4u;
    const int c4 = (tid & 7) * 4;
#pragma unroll 2
    for (int m = tid >> 3; m < NR; m += 32) {
        int gr = R0 - P + m;
        gr = gr < 0 ? -gr : (gr > H - 1 ? 2 * H - 2 - gr : gr);
        cp_async16(base + (unsigned)(m * 32 + c4) * 4u,
                   src + (size_t)gr * W + c4);
    }
    cp_commit();
}

template <int KS>
__device__ __forceinline__ void vconv(const Wt<KS> Wc,
                                      const float* __restrict__ sm,
                                      int g, int lane, float acc[8]) {
    const int base = g * 8 * 32 + lane;
    float win[8];
#pragma unroll
    for (int i = 0; i < 7; ++i) win[i] = sm[base + i * 32];
#pragma unroll
    for (int t = 0; t < 8; ++t) acc[t] = 0.f;
#pragma unroll
    for (int k = 0; k < KS; ++k) {
        win[(k + 7) & 7] = sm[base + (k + 7) * 32];
#pragma unroll
        for (int t = 0; t < 8; ++t)
            acc[t] += Wc.w[k] * win[(k + t) & 7];
    }
}

// band_{s+1} = prev - cur ; then prev <- cur
__device__ __forceinline__ void store_desc(float* __restrict__ p,
                                           const float cur[8], float prev[8]) {
#pragma unroll
    for (int t = 0; t < 8; ++t) {
        p[(size_t)t * W] = prev[t] - cur[t];
        prev[t] = cur[t];
    }
}

__global__ __launch_bounds__(256) void vpass_kernel(const float* __restrict__ img,
                                                    float* __restrict__ out) {
    extern __shared__ float sm[];
    const int tid  = threadIdx.x;
    const int lane = tid & 31;
    const int g    = tid >> 5;
    const int c0   = blockIdx.x * 32;
    const int R0   = blockIdx.y * 64;
    const int bc   = blockIdx.z;
    const int b    = bc / 3;
    const int ch   = bc - b * 3;
    const int rbase = R0 + g * 8;

    const float* sbase = g_scratch + (size_t)bc * HW + c0;
    const unsigned smb = (unsigned)__cvta_generic_to_shared(sm);

    // kick off the two largest tiles
    load_tile_async<117, BUFA>(smb, sbase + 5 * (size_t)NPIX, R0, tid);
    load_tile_async<59,  BUFB>(smb, sbase + 4 * (size_t)NPIX, R0, tid);

    // img values for band0 (held in regs; LDG overlaps the cp.asyncs)
    const float* imgp = img + (size_t)bc * HW + c0 + lane;
    float imgv[8];
#pragma unroll
    for (int t = 0; t < 8; ++t) imgv[t] = imgp[(size_t)(rbase + t) * W];

    float prev[8], cur[8];
    float* outp = out + ((size_t)b * 21 + ch) * HW + (size_t)rbase * W + c0 + lane;

    // ---- sigma5 (A): band6 = G5
    cp_wait<1>(); __syncthreads();
    vconv<117>(CW5, sm + BUFA, g, lane, cur);
#pragma unroll
    for (int t = 0; t < 8; ++t) {
        outp[6 * (size_t)(3 * HW) + (size_t)t * W] = cur[t];
        prev[t] = cur[t];
    }
    __syncthreads();
    load_tile_async<31, BUFA>(smb, sbase + 3 * (size_t)NPIX, R0, tid);

    // ---- sigma4 (B): band5 = G5 - G4
    cp_wait<1>(); __syncthreads();
    vconv<59>(CW4, sm + BUFB, g, lane, cur);
    store_desc(outp + 5 * (size_t)(3 * HW), cur, prev);
    __syncthreads();
    load_tile_async<17, BUFB>(smb, sbase + 2 * (size_t)NPIX, R0, tid);

    // ---- sigma3 (A): band4 = G4 - G3
    cp_wait<1>(); __syncthreads();
    vconv<31>(CW3, sm + BUFA, g, lane, cur);
    store_desc(outp + 4 * (size_t)(3 * HW), cur, prev);
    __syncthreads();
    load_tile_async<9, BUFA>(smb, sbase + 1 * (size_t)NPIX, R0, tid);

    // ---- sigma2 (B): band3 = G3 - G2
    cp_wait<1>(); __syncthreads();
    vconv<17>(CW2, sm + BUFB, g, lane, cur);
    store_desc(outp + 3 * (size_t)(3 * HW), cur, prev);
    __syncthreads();
    load_tile_async<7, BUFB>(smb, sbase + 0 * (size_t)NPIX, R0, tid);

    // ---- sigma1 (A): band2 = G2 - G1
    cp_wait<1>(); __syncthreads();
    vconv<9>(CW1, sm + BUFA, g, lane, cur);
    store_desc(outp + 2 * (size_t)(3 * HW), cur, prev);

    // ---- sigma0 (B): band1 = G1 - G0
    cp_wait<0>(); __syncthreads();
    vconv<7>(CW0, sm + BUFB, g, lane, cur);
    store_desc(outp + 1 * (size_t)(3 * HW), cur, prev);

    // band0 = G0 - img (prev now holds G0)
#pragma unroll
    for (int t = 0; t < 8; ++t)
        outp[(size_t)t * W] = prev[t] - imgv[t];
}

// ---------------------------------------------------------------------------
extern "C" void kernel_launch(void* const* d_in, const int* in_sizes, int n_in,
                              void* d_out, int out_size) {
    const float* img = (const float*)d_in[0];
    float* out = (float*)d_out;

    cudaFuncSetAttribute(vpass_kernel,
                         cudaFuncAttributeMaxDynamicSharedMemorySize,
                         VSMEM_BYTES);

    hpass_kernel<<<HGRID, 256>>>(img);
    vpass_kernel<<<dim3(W / 32, H / 64, 8 * 3), 256, VSMEM_BYTES>>>(img, out);
}

// round 11
// speedup vs baseline: 1.3338x; 1.3338x over previous
#include <cuda_runtime.h>
#include <cstddef>

// ---------------------------------------------------------------------------
// Compile-time Gaussian weights (passed BY VALUE so they fold to FFMA-imm)
// ---------------------------------------------------------------------------
constexpr double cexp_pos(double x) {
    double term = 1.0, sum = 1.0;
    for (int i = 1; i < 200; ++i) {
        term *= x / (double)i;
        if (term < 1e-250) break;
        sum += term;
    }
    return sum;
}

template <int KS>
struct Wt { float w[KS]; };

template <int KS>
constexpr Wt<KS> make_w(double sigma) {
    Wt<KS> W{};
    double wd[KS]{};
    double s = 0.0;
    for (int i = 0; i < KS; ++i) {
        double d = (double)(i - KS / 2);
        double e = 1.0 / cexp_pos(d * d / (2.0 * sigma * sigma));
        wd[i] = e;
        s += e;
    }
    for (int i = 0; i < KS; ++i) W.w[i] = (float)(wd[i] / s);
    return W;
}

constexpr Wt<7>   CW0 = make_w<7>(0.6);
constexpr Wt<9>   CW1 = make_w<9>(1.2);
constexpr Wt<17>  CW2 = make_w<17>(2.4);
constexpr Wt<31>  CW3 = make_w<31>(4.8);
constexpr Wt<59>  CW4 = make_w<59>(9.6);
constexpr Wt<117> CW5 = make_w<117>(19.2);

constexpr int H = 512, W = 512;
constexpr int HW = H * W;
constexpr int NROWS = 8 * 3 * H;        // 12288
constexpr int NPIX = NROWS * W;         // 6291456
constexpr int PMAX = 58;

__device__ float g_scratch[6 * (size_t)NPIX];

// ---------------------------------------------------------------------------
// cp.async helpers
// ---------------------------------------------------------------------------
__device__ __forceinline__ void cp_async16(unsigned daddr, const void* gsrc) {
    asm volatile("cp.async.cg.shared.global [%0], [%1], 16;\n"
                 :: "r"(daddr), "l"(gsrc) : "memory");
}
__device__ __forceinline__ void cp_commit() {
    asm volatile("cp.async.commit_group;\n" ::: "memory");
}
template <int N>
__device__ __forceinline__ void cp_wait() {
    asm volatile("cp.async.wait_group %0;\n" :: "n"(N) : "memory");
}

// ---------------------------------------------------------------------------
// Kernel A: horizontal pass (round-8 structure; reg-capped for 5 CTAs/SM).
// CTA = 256 = 4 rows x 64 threads; 8 px/thread. Padded smem row
// (idx -> idx + idx/8): stride-8 lane access conflict-free (stride 9).
// ---------------------------------------------------------------------------
template <int KS>
__device__ __forceinline__ void hconv(const Wt<KS> Wc,
                                      const float* __restrict__ sr,
                                      int lane, float* __restrict__ dst) {
    constexpr int P  = KS / 2;
    constexpr int S0 = PMAX - P;
    constexpr int Q  = S0 >> 3;
    constexpr int R  = S0 & 7;
    const int base = 9 * (lane + Q);

    float win[8], acc[8];
#pragma unroll
    for (int i = 0; i < 7; ++i)
        win[i] = sr[base + (R + i) + ((R + i) >> 3)];
#pragma unroll
    for (int t = 0; t < 8; ++t) acc[t] = 0.f;
#pragma unroll
    for (int k = 0; k < KS; ++k) {
        const int j = k + 7;
        win[j & 7] = sr[base + (R + j) + ((R + j) >> 3)];
#pragma unroll
        for (int t = 0; t < 8; ++t)
            acc[t] += Wc.w[k] * win[(k + t) & 7];
    }
    float4* d4 = reinterpret_cast<float4*>(dst + lane * 8);
    d4[0] = make_float4(acc[0], acc[1], acc[2], acc[3]);
    d4[1] = make_float4(acc[4], acc[5], acc[6], acc[7]);
}

__global__ __launch_bounds__(256, 5) void hpass_kernel(const float* __restrict__ img) {
    __shared__ float sr[4][712];
    const int grp = threadIdx.x >> 6;
    const int lt  = threadIdx.x & 63;
    const int row = blockIdx.x * 4 + grp;

    const float* rp = img + (size_t)row * W;
    for (int x = lt; x < W + 2 * PMAX; x += 64) {
        int gx = x - PMAX;
        gx = gx < 0 ? -gx : (gx > W - 1 ? 2 * W - 2 - gx : gx);
        sr[grp][x + (x >> 3)] = rp[gx];
    }
    __syncthreads();

    const float* s = sr[grp];
    float* base = g_scratch + (size_t)row * W;
    hconv<7>(CW0, s, lt, base + 0 * (size_t)NPIX);
    hconv<9>(CW1, s, lt, base + 1 * (size_t)NPIX);
    hconv<17>(CW2, s, lt, base + 2 * (size_t)NPIX);
    hconv<31>(CW3, s, lt, base + 3 * (size_t)NPIX);
    hconv<59>(CW4, s, lt, base + 4 * (size_t)NPIX);
    hconv<117>(CW5, s, lt, base + 5 * (size_t)NPIX);
}

// ---------------------------------------------------------------------------
// Kernel B: vertical pass + DoG, double-buffered, DESCENDING sigma order
// (exact round-8 proven version: 71.4 us).
// Slot A (180 rows) holds sigma 5,3,1 tiles; slot B (122 rows) holds 4,2,0.
// smem = 302 rows * 128 B = 38656 B -> 5 CTAs/SM.
// ---------------------------------------------------------------------------
constexpr int VSMEM_BYTES = 302 * 32 * 4;    // 38656
constexpr int BUFA = 0;                       // 180 rows
constexpr int BUFB = 180 * 32;                // 122 rows

template <int KS, int OFF>
__device__ __forceinline__ void load_tile_async(unsigned smb,
                                                const float* __restrict__ src,
                                                int R0, int tid) {
    constexpr int P  = KS / 2;
    constexpr int NR = 64 + KS - 1;
    const unsigned base = smb + (unsigned)OFF * 4u;
    const int c4 = (tid & 7) * 4;
#pragma unroll 2
    for (int m = tid >> 3; m < NR; m += 32) {
        int gr = R0 - P + m;
        gr = gr < 0 ? -gr : (gr > H - 1 ? 2 * H - 2 - gr : gr);
        cp_async16(base + (unsigned)(m * 32 + c4) * 4u,
                   src + (size_t)gr * W + c4);
    }
    cp_commit();
}

template <int KS>
__device__ __forceinline__ void vconv(const Wt<KS> Wc,
                                      const float* __restrict__ sm,
                                      int g, int lane, float acc[8]) {
    const int base = g * 8 * 32 + lane;
    float win[8];
#pragma unroll
    for (int i = 0; i < 7; ++i) win[i] = sm[base + i * 32];
#pragma unroll
    for (int t = 0; t < 8; ++t) acc[t] = 0.f;
#pragma unroll
    for (int k = 0; k < KS; ++k) {
        win[(k + 7) & 7] = sm[base + (k + 7) * 32];
#pragma unroll
        for (int t = 0; t < 8; ++t)
            acc[t] += Wc.w[k] * win[(k + t) & 7];
    }
}

// band_{s+1} = prev - cur ; then prev <- cur
__device__ __forceinline__ void store_desc(float* __restrict__ p,
                                           const float cur[8], float prev[8]) {
#pragma unroll
    for (int t = 0; t < 8; ++t) {
        p[(size_t)t * W] = prev[t] - cur[t];
        prev[t] = cur[t];
    }
}

__global__ __launch_bounds__(256) void vpass_kernel(const float* __restrict__ img,
                                                    float* __restrict__ out) {
    extern __shared__ float sm[];
    const int tid  = threadIdx.x;
    const int lane = tid & 31;
    const int g    = tid >> 5;
    const int c0   = blockIdx.x * 32;
    const int R0   = blockIdx.y * 64;
    const int bc   = blockIdx.z;
    const int b    = bc / 3;
    const int ch   = bc - b * 3;
    const int rbase = R0 + g * 8;

    const float* sbase = g_scratch + (size_t)bc * HW + c0;
    const unsigned smb = (unsigned)__cvta_generic_to_shared(sm);

    // kick off the two largest tiles
    load_tile_async<117, BUFA>(smb, sbase + 5 * (size_t)NPIX, R0, tid);
    load_tile_async<59,  BUFB>(smb, sbase + 4 * (size_t)NPIX, R0, tid);

    // img values for band0 (held in regs; LDG overlaps the cp.asyncs)
    const float* imgp = img + (size_t)bc * HW + c0 + lane;
    float imgv[8];
#pragma unroll
    for (int t = 0; t < 8; ++t) imgv[t] = imgp[(size_t)(rbase + t) * W];

    float prev[8], cur[8];
    float* outp = out + ((size_t)b * 21 + ch) * HW + (size_t)rbase * W + c0 + lane;

    // ---- sigma5 (A): band6 = G5
    cp_wait<1>(); __syncthreads();
    vconv<117>(CW5, sm + BUFA, g, lane, cur);
#pragma unroll
    for (int t = 0; t < 8; ++t) {
        outp[6 * (size_t)(3 * HW) + (size_t)t * W] = cur[t];
        prev[t] = cur[t];
    }
    __syncthreads();
    load_tile_async<31, BUFA>(smb, sbase + 3 * (size_t)NPIX, R0, tid);

    // ---- sigma4 (B): band5 = G5 - G4
    cp_wait<1>(); __syncthreads();
    vconv<59>(CW4, sm + BUFB, g, lane, cur);
    store_desc(outp + 5 * (size_t)(3 * HW), cur, prev);
    __syncthreads();
    load_tile_async<17, BUFB>(smb, sbase + 2 * (size_t)NPIX, R0, tid);

    // ---- sigma3 (A): band4 = G4 - G3
    cp_wait<1>(); __syncthreads();
    vconv<31>(CW3, sm + BUFA, g, lane, cur);
    store_desc(outp + 4 * (size_t)(3 * HW), cur, prev);
    __syncthreads();
    load_tile_async<9, BUFA>(smb, sbase + 1 * (size_t)NPIX, R0, tid);

    // ---- sigma2 (B): band3 = G3 - G2
    cp_wait<1>(); __syncthreads();
    vconv<17>(CW2, sm + BUFB, g, lane, cur);
    store_desc(outp + 3 * (size_t)(3 * HW), cur, prev);
    __syncthreads();
    load_tile_async<7, BUFB>(smb, sbase + 0 * (size_t)NPIX, R0, tid);

    // ---- sigma1 (A): band2 = G2 - G1
    cp_wait<1>(); __syncthreads();
    vconv<9>(CW1, sm + BUFA, g, lane, cur);
    store_desc(outp + 2 * (size_t)(3 * HW), cur, prev);

    // ---- sigma0 (B): band1 = G1 - G0
    cp_wait<0>(); __syncthreads();
    vconv<7>(CW0, sm + BUFB, g, lane, cur);
    store_desc(outp + 1 * (size_t)(3 * HW), cur, prev);

    // band0 = G0 - img (prev now holds G0)
#pragma unroll
    for (int t = 0; t < 8; ++t)
        outp[(size_t)t * W] = prev[t] - imgv[t];
}

// ---------------------------------------------------------------------------
extern "C" void kernel_launch(void* const* d_in, const int* in_sizes, int n_in,
                              void* d_out, int out_size) {
    const float* img = (const float*)d_in[0];
    float* out = (float*)d_out;

    cudaFuncSetAttribute(vpass_kernel,
                         cudaFuncAttributeMaxDynamicSharedMemorySize,
                         VSMEM_BYTES);

    hpass_kernel<<<NROWS / 4, 256>>>(img);
    vpass_kernel<<<dim3(W / 32, H / 64, 8 * 3), 256, VSMEM_BYTES>>>(img, out);
}

// round 12
// speedup vs baseline: 1.5855x; 1.1887x over previous
#include <cuda_runtime.h>
#include <cuda_fp16.h>
#include <cstddef>

// ---------------------------------------------------------------------------
// Compile-time Gaussian weights (passed BY VALUE so they fold to FFMA-imm)
// ---------------------------------------------------------------------------
constexpr double cexp_pos(double x) {
    double term = 1.0, sum = 1.0;
    for (int i = 1; i < 200; ++i) {
        term *= x / (double)i;
        if (term < 1e-250) break;
        sum += term;
    }
    return sum;
}

template <int KS>
struct Wt { float w[KS]; };

template <int KS>
constexpr Wt<KS> make_w(double sigma) {
    Wt<KS> W{};
    double wd[KS]{};
    double s = 0.0;
    for (int i = 0; i < KS; ++i) {
        double d = (double)(i - KS / 2);
        double e = 1.0 / cexp_pos(d * d / (2.0 * sigma * sigma));
        wd[i] = e;
        s += e;
    }
    for (int i = 0; i < KS; ++i) W.w[i] = (float)(wd[i] / s);
    return W;
}

constexpr Wt<7>   CW0 = make_w<7>(0.6);
constexpr Wt<9>   CW1 = make_w<9>(1.2);
constexpr Wt<17>  CW2 = make_w<17>(2.4);
constexpr Wt<31>  CW3 = make_w<31>(4.8);
constexpr Wt<59>  CW4 = make_w<59>(9.6);
constexpr Wt<117> CW5 = make_w<117>(19.2);

constexpr int H = 512, W = 512;
constexpr int HW = H * W;
constexpr int NROWS = 8 * 3 * H;        // 12288
constexpr int NPIX = NROWS * W;         // 6291456
constexpr int PMAX = 58;

// fp16 h-blurred planes (75.5 MB)
__device__ __align__(16) __half g_scratch[6 * (size_t)NPIX];

// ---------------------------------------------------------------------------
// cp.async helpers
// ---------------------------------------------------------------------------
__device__ __forceinline__ void cp_async16(unsigned daddr, const void* gsrc) {
    asm volatile("cp.async.cg.shared.global [%0], [%1], 16;\n"
                 :: "r"(daddr), "l"(gsrc) : "memory");
}
__device__ __forceinline__ void cp_commit() {
    asm volatile("cp.async.commit_group;\n" ::: "memory");
}
template <int N>
__device__ __forceinline__ void cp_wait() {
    asm volatile("cp.async.wait_group %0;\n" :: "n"(N) : "memory");
}

// ---------------------------------------------------------------------------
// Kernel A: horizontal pass (round-8 proven structure, fp16 output).
// CTA = 256 = 4 rows x 64 threads; 8 px/thread. Padded smem row
// (idx -> idx + idx/8): stride-8 lane access conflict-free (stride 9).
// ---------------------------------------------------------------------------
template <int KS>
__device__ __forceinline__ void hconv(const Wt<KS> Wc,
                                      const float* __restrict__ sr,
                                      int lane, __half* __restrict__ dst) {
    constexpr int P  = KS / 2;
    constexpr int S0 = PMAX - P;
    constexpr int Q  = S0 >> 3;
    constexpr int R  = S0 & 7;
    const int base = 9 * (lane + Q);

    float win[8], acc[8];
#pragma unroll
    for (int i = 0; i < 7; ++i)
        win[i] = sr[base + (R + i) + ((R + i) >> 3)];
#pragma unroll
    for (int t = 0; t < 8; ++t) acc[t] = 0.f;
#pragma unroll
    for (int k = 0; k < KS; ++k) {
        const int j = k + 7;
        win[j & 7] = sr[base + (R + j) + ((R + j) >> 3)];
#pragma unroll
        for (int t = 0; t < 8; ++t)
            acc[t] += Wc.w[k] * win[(k + t) & 7];
    }
    __half2 hh[4];
#pragma unroll
    for (int q = 0; q < 4; ++q)
        hh[q] = __floats2half2_rn(acc[2 * q], acc[2 * q + 1]);
    *reinterpret_cast<float4*>(dst + lane * 8) =
        *reinterpret_cast<const float4*>(hh);
}

__global__ __launch_bounds__(256, 4) void hpass_kernel(const float* __restrict__ img) {
    __shared__ float sr[4][712];
    const int grp = threadIdx.x >> 6;
    const int lt  = threadIdx.x & 63;
    const int row = blockIdx.x * 4 + grp;

    const float* rp = img + (size_t)row * W;
    for (int x = lt; x < W + 2 * PMAX; x += 64) {
        int gx = x - PMAX;
        gx = gx < 0 ? -gx : (gx > W - 1 ? 2 * W - 2 - gx : gx);
        sr[grp][x + (x >> 3)] = rp[gx];
    }
    __syncthreads();

    const float* s = sr[grp];
    __half* base = g_scratch + (size_t)row * W;
    hconv<7>(CW0, s, lt, base + 0 * (size_t)NPIX);
    hconv<9>(CW1, s, lt, base + 1 * (size_t)NPIX);
    hconv<17>(CW2, s, lt, base + 2 * (size_t)NPIX);
    hconv<31>(CW3, s, lt, base + 3 * (size_t)NPIX);
    hconv<59>(CW4, s, lt, base + 4 * (size_t)NPIX);
    hconv<117>(CW5, s, lt, base + 5 * (size_t)NPIX);
}

// ---------------------------------------------------------------------------
// Kernel B: vertical pass + DoG, double-buffered, DESCENDING sigma order,
// fp16 smem tiles (half the footprint -> ~8 CTAs/SM).
// Slot A (180 rows) holds sigma 5,3,1 tiles; slot B (122 rows) holds 4,2,0.
// smem = 302 rows * 64 B = 19328 B.
// ---------------------------------------------------------------------------
constexpr int VSMEM_BYTES = 302 * 32 * 2;    // 19328
constexpr int BUFA = 0;                       // 180 rows (half index)
constexpr int BUFB = 180 * 32;                // 122 rows

template <int KS, int OFF>
__device__ __forceinline__ void load_tile_async(unsigned smb,
                                                const __half* __restrict__ src,
                                                int R0, int tid) {
    constexpr int P  = KS / 2;
    constexpr int NR = 64 + KS - 1;
    const unsigned base = smb + (unsigned)OFF * 2u;
    const int c8 = (tid & 3) * 8;            // half offset of this thread's 16B
#pragma unroll 2
    for (int m = tid >> 2; m < NR; m += 64) {
        int gr = R0 - P + m;
        gr = gr < 0 ? -gr : (gr > H - 1 ? 2 * H - 2 - gr : gr);
        cp_async16(base + (unsigned)(m * 32 + c8) * 2u,
                   src + (size_t)gr * W + c8);
    }
    cp_commit();
}

template <int KS>
__device__ __forceinline__ void vconv(const Wt<KS> Wc,
                                      const __half* __restrict__ smh,
                                      int g, int lane, float acc[8]) {
    const int base = g * 8 * 32 + lane;
    float win[8];
#pragma unroll
    for (int i = 0; i < 7; ++i) win[i] = __half2float(smh[base + i * 32]);
#pragma unroll
    for (int t = 0; t < 8; ++t) acc[t] = 0.f;
#pragma unroll
    for (int k = 0; k < KS; ++k) {
        win[(k + 7) & 7] = __half2float(smh[base + (k + 7) * 32]);
#pragma unroll
        for (int t = 0; t < 8; ++t)
            acc[t] += Wc.w[k] * win[(k + t) & 7];
    }
}

// band_{s+1} = prev - cur ; then prev <- cur
__device__ __forceinline__ void store_desc(float* __restrict__ p,
                                           const float cur[8], float prev[8]) {
#pragma unroll
    for (int t = 0; t < 8; ++t) {
        p[(size_t)t * W] = prev[t] - cur[t];
        prev[t] = cur[t];
    }
}

__global__ __launch_bounds__(256) void vpass_kernel(const float* __restrict__ img,
                                                    float* __restrict__ out) {
    extern __shared__ __half smh[];
    const int tid  = threadIdx.x;
    const int lane = tid & 31;
    const int g    = tid >> 5;
    const int c0   = blockIdx.x * 32;
    const int R0   = blockIdx.y * 64;
    const int bc   = blockIdx.z;
    const int b    = bc / 3;
    const int ch   = bc - b * 3;
    const int rbase = R0 + g * 8;

    const __half* sbase = g_scratch + (size_t)bc * HW + c0;
    const unsigned smb = (unsigned)__cvta_generic_to_shared(smh);

    // kick off the two largest tiles
    load_tile_async<117, BUFA>(smb, sbase + 5 * (size_t)NPIX, R0, tid);
    load_tile_async<59,  BUFB>(smb, sbase + 4 * (size_t)NPIX, R0, tid);

    // img values for band0 (held in regs; LDG overlaps the cp.asyncs)
    const float* imgp = img + (size_t)bc * HW + c0 + lane;
    float imgv[8];
#pragma unroll
    for (int t = 0; t < 8; ++t) imgv[t] = imgp[(size_t)(rbase + t) * W];

    float prev[8], cur[8];
    float* outp = out + ((size_t)b * 21 + ch) * HW + (size_t)rbase * W + c0 + lane;

    // ---- sigma5 (A): band6 = G5
    cp_wait<1>(); __syncthreads();
    vconv<117>(CW5, smh + BUFA, g, lane, cur);
#pragma unroll
    for (int t = 0; t < 8; ++t) {
        outp[6 * (size_t)(3 * HW) + (size_t)t * W] = cur[t];
        prev[t] = cur[t];
    }
    __syncthreads();
    load_tile_async<31, BUFA>(smb, sbase + 3 * (size_t)NPIX, R0, tid);

    // ---- sigma4 (B): band5 = G5 - G4
    cp_wait<1>(); __syncthreads();
    vconv<59>(CW4, smh + BUFB, g, lane, cur);
    store_desc(outp + 5 * (size_t)(3 * HW), cur, prev);
    __syncthreads();
    load_tile_async<17, BUFB>(smb, sbase + 2 * (size_t)NPIX, R0, tid);

    // ---- sigma3 (A): band4 = G4 - G3
    cp_wait<1>(); __syncthreads();
    vconv<31>(CW3, smh + BUFA, g, lane, cur);
    store_desc(outp + 4 * (size_t)(3 * HW), cur, prev);
    __syncthreads();
    load_tile_async<9, BUFA>(smb, sbase + 1 * (size_t)NPIX, R0, tid);

    // ---- sigma2 (B): band3 = G3 - G2
    cp_wait<1>(); __syncthreads();
    vconv<17>(CW2, smh + BUFB, g, lane, cur);
    store_desc(outp + 3 * (size_t)(3 * HW), cur, prev);
    __syncthreads();
    load_tile_async<7, BUFB>(smb, sbase + 0 * (size_t)NPIX, R0, tid);

    // ---- sigma1 (A): band2 = G2 - G1
    cp_wait<1>(); __syncthreads();
    vconv<9>(CW1, smh + BUFA, g, lane, cur);
    store_desc(outp + 2 * (size_t)(3 * HW), cur, prev);

    // ---- sigma0 (B): band1 = G1 - G0
    cp_wait<0>(); __syncthreads();
    vconv<7>(CW0, smh + BUFB, g, lane, cur);
    store_desc(outp + 1 * (size_t)(3 * HW), cur, prev);

    // band0 = G0 - img (prev now holds G0)
#pragma unroll
    for (int t = 0; t < 8; ++t)
        outp[(size_t)t * W] = prev[t] - imgv[t];
}

// ---------------------------------------------------------------------------
extern "C" void kernel_launch(void* const* d_in, const int* in_sizes, int n_in,
                              void* d_out, int out_size) {
    const float* img = (const float*)d_in[0];
    float* out = (float*)d_out;

    cudaFuncSetAttribute(vpass_kernel,
                         cudaFuncAttributeMaxDynamicSharedMemorySize,
                         VSMEM_BYTES);

    hpass_kernel<<<NROWS / 4, 256>>>(img);
    vpass_kernel<<<dim3(W / 32, H / 64, 8 * 3), 256, VSMEM_BYTES>>>(img, out);
}